// round 14
// baseline (speedup 1.0000x reference)
#include <cuda_runtime.h>
#include <cstdint>

#define NFACE 1024
#define NB 2
#define NBLK (NB * 512)

// Preprocessed per-face records (7 x float4) + dilated bboxes.
// NOTE: written and read within the SAME kernel -> consumers must use plain
// generic loads (NOT __ldg / ld.global.nc, whose immutability contract we'd
// violate — that was R12's correctness bug).
__device__ float4 g_face[NB * NFACE * 7];
__device__ float4 g_bbox[NB * NFACE];
__device__ int g_ready;   // prep blocks done (0..8); reset by last block
__device__ int g_done;    // raster blocks done; reset by last block

// Constants: SIGMA=1e-5, GAMMA=1e-4, EPS=1e-3, NEAR=1, FAR=100, DIST_EPS=1e-4
#define F_EPS   1e-3f
#define K2      14426.950408889634f     /* log2(e)/GAMMA */
#define CSIG    144269.50408889634f     /* log2(e)/SIGMA */
#define THR     9.2102404e-05f          /* SIGMA*ln(1/DIST_EPS - 1) */
#define BB_PAD  0.0096f                 /* >= sqrt(THR) */

__device__ __forceinline__ float fexp2(float x) {
    float y; asm("ex2.approx.ftz.f32 %0, %1;" : "=f"(y) : "f"(x)); return y;
}
__device__ __forceinline__ float frcp(float x) {
    float y; asm("rcp.approx.ftz.f32 %0, %1;" : "=f"(y) : "f"(x)); return y;
}
__device__ __forceinline__ float frcp_nr(float x) {
    float r = frcp(x);
    return r * (2.0f - x * r);
}

// ---------------------------------------------------------------------------
// Single fused kernel. Grid: 1024 blocks (8x4 px tiles), 256 threads.
// Blocks 0..7 additionally run prep (1 face per thread) before rastering.
// All blocks gate their raster phase on g_ready == 8 via acquire-load spin.
// Record layout (7 float4):
//  r0: x0 y0 x1 y1 | r1: x2 y2 e2y/det e2x/det | r2: e1x/det e1y/det iL01 iL12
//  r3: iL20 iz0 iz1 iz2 | r4..r6: textures
// ---------------------------------------------------------------------------
__global__ void __launch_bounds__(256)
fused_kernel(const float* __restrict__ fv,
             const float* __restrict__ tex,
             float* __restrict__ out) {
    __shared__ unsigned short seg[8][128];
    __shared__ unsigned short flat[NFACE];
    __shared__ int counts[8];
    __shared__ float red[6][8][36];   // [field][warp-partial][pixel] (padded)

    const int tid  = threadIdx.x;
    const int lane = tid & 31;
    const int wi   = tid >> 5;
    const int bidx = blockIdx.x;

    // ---- Prep duty: blocks 0..7, one face per thread (2048 faces) ----
    if (bidx < 8) {
        const int i = bidx * 256 + tid;
        const float* v = fv + i * 9;
        float x0 = v[0], y0 = v[1], z0 = v[2];
        float x1 = v[3], y1 = v[4], z1 = v[5];
        float x2 = v[6], y2 = v[7], z2 = v[8];

        float e1x = x1 - x0, e1y = y1 - y0;
        float e2x = x2 - x0, e2y = y2 - y0;
        float det = e1x * e2y - e1y * e2x;
        if (fabsf(det) < 1e-10f) det = 1e-10f;
        float inv = 1.0f / det;

        float e12x = x2 - x1, e12y = y2 - y1;
        float e20x = x0 - x2, e20y = y0 - y2;
        float iL01 = 1.0f / fmaxf(e1x * e1x + e1y * e1y, 1e-12f);
        float iL12 = 1.0f / fmaxf(e12x * e12x + e12y * e12y, 1e-12f);
        float iL20 = 1.0f / fmaxf(e20x * e20x + e20y * e20y, 1e-12f);

        const float* t = tex + i * 9;
        float4* fr = g_face + i * 7;
        fr[0] = make_float4(x0, y0, x1, y1);
        fr[1] = make_float4(x2, y2, e2y * inv, e2x * inv);
        fr[2] = make_float4(e1x * inv, e1y * inv, iL01, iL12);
        fr[3] = make_float4(iL20, 1.0f / z0, 1.0f / z1, 1.0f / z2);
        fr[4] = make_float4(t[0], t[1], t[2], t[3]);
        fr[5] = make_float4(t[4], t[5], t[6], t[7]);
        fr[6] = make_float4(t[8], 0.0f, 0.0f, 0.0f);

        float xmn = fminf(x0, fminf(x1, x2)) - BB_PAD;
        float xmx = fmaxf(x0, fmaxf(x1, x2)) + BB_PAD;
        float ymn = fminf(y0, fminf(y1, y2)) - BB_PAD;
        float ymx = fmaxf(y0, fmaxf(y1, y2)) + BB_PAD;
        g_bbox[i] = make_float4(xmn, ymn, xmx, ymx);

        __syncthreads();
        __threadfence();                       // release all prep stores
        if (tid == 0) atomicAdd(&g_ready, 1);
    }

    // ---- Tile coordinates (independent of prep) ----
    const int batch = bidx >> 9;
    const int tile  = bidx & 511;
    const int tx    = tile & 15;          // 16 tiles across (8 px wide)
    const int ty    = tile >> 4;          // 32 tiles down  (4 px tall)

    const int lx = lane & 7;
    const int ly = lane >> 3;
    const float px = (float)(2 * (tx * 8 + lx) + 1 - 128) * (1.0f / 128.0f);
    const float py = -(float)(2 * (ty * 4 + ly) + 1 - 128) * (1.0f / 128.0f);

    const float txmin = (float)(2 * (tx * 8) + 1 - 128) * (1.0f / 128.0f);
    const float txmax = (float)(2 * (tx * 8 + 7) + 1 - 128) * (1.0f / 128.0f);
    const float tymax = -(float)(2 * (ty * 4) + 1 - 128) * (1.0f / 128.0f);
    const float tymin = -(float)(2 * (ty * 4 + 3) + 1 - 128) * (1.0f / 128.0f);

    // ---- Gate: acquire-load spin until all 8 prep blocks have released ----
    if (tid == 0) {
        for (;;) {
            int v;
            asm volatile("ld.acquire.gpu.global.s32 %0, [%1];"
                         : "=r"(v) : "l"(&g_ready) : "memory");
            if (v >= 8) break;
            __nanosleep(64);
        }
    }
    __syncthreads();   // extend thread-0's acquire to the whole block

    const float4* bb = g_bbox + batch * NFACE;
    const float4* fr = g_face + (size_t)batch * NFACE * 7;

    // ---- Phase 1: lane-parallel bbox cull + deterministic compaction ----
    const int f0 = wi * 128;
    int cnt = 0;
    #pragma unroll
    for (int it = 0; it < 4; ++it) {
        const int f = f0 + it * 32 + lane;
        const float4 b = bb[f];                       // plain load (see note)
        const bool hit = !(b.x > txmax || b.z < txmin || b.y > tymax || b.w < tymin);
        const unsigned msk = __ballot_sync(0xffffffffu, hit);
        if (hit) {
            const int pos = cnt + __popc(msk & ((1u << lane) - 1u));
            seg[wi][pos] = (unsigned short)f;
        }
        cnt += __popc(msk);
    }
    if (lane == 0) counts[wi] = cnt;
    __syncthreads();

    int base = 0, T = 0;
    #pragma unroll
    for (int i = 0; i < 8; ++i) {
        const int c = counts[i];
        if (i < wi) base += c;
        T += c;
    }
    for (int k = lane; k < cnt; k += 32) flat[base + k] = seg[wi][k];
    __syncthreads();

    // ---- Phase 2: evaluation over flat list, round-robin per warp (R2) ----
    float m = F_EPS;
    float wsum = 0.0f, cr = 0.0f, cg = 0.0f, cb = 0.0f;
    float pa = 1.0f;

    for (int j = wi; j < T; j += 8) {
        const int f = flat[j];

        const float4 r0 = fr[f * 7 + 0];
        const float4 r1 = fr[f * 7 + 1];
        const float4 r2 = fr[f * 7 + 2];
        const float4 r3 = fr[f * 7 + 3];

        const float x0 = r0.x, y0 = r0.y, x1 = r0.z, y1 = r0.w;
        const float x2 = r1.x, y2 = r1.y;

        const float dx = px - x0, dy = py - y0;
        const float w1 = dx * r1.z - dy * r1.w;
        const float w2 = dy * r2.x - dx * r2.y;
        const float w0 = 1.0f - w1 - w2;
        const bool inside = (w0 >= 0.0f) && (w1 >= 0.0f) && (w2 >= 0.0f);

        float ex = x1 - x0, ey = y1 - y0;
        float t  = __saturatef((dx * ex + dy * ey) * r2.z);
        float qx = dx - t * ex, qy = dy - t * ey;
        float dis = qx * qx + qy * qy;

        ex = x2 - x1; ey = y2 - y1;
        const float dx1 = px - x1, dy1 = py - y1;
        t  = __saturatef((dx1 * ex + dy1 * ey) * r2.w);
        qx = dx1 - t * ex; qy = dy1 - t * ey;
        dis = fminf(dis, qx * qx + qy * qy);

        ex = x0 - x2; ey = y0 - y2;
        const float dx2 = px - x2, dy2 = py - y2;
        t  = __saturatef((dx2 * ex + dy2 * ey) * r3.x);
        qx = dx2 - t * ex; qy = dy2 - t * ey;
        dis = fminf(dis, qx * qx + qy * qy);

        const bool near = inside || (dis <= THR);
        if (__all_sync(0xffffffffu, !near)) continue;

        const float sarg = inside ? (-dis * CSIG) : (dis * CSIG);
        const float D = frcp(1.0f + fexp2(sarg));

        pa *= near ? (1.0f - D) : 1.0f;

        float c0 = __saturatef(w0), c1 = __saturatef(w1), c2 = __saturatef(w2);
        const float rs = frcp_nr(fmaxf(c0 + c1 + c2, 1e-5f));
        c0 *= rs; c1 *= rs; c2 *= rs;

        const float invz = c0 * r3.y + c1 * r3.z + c2 * r3.w;
        const float zp = frcp_nr(fmaxf(invz, 1e-8f));
        const bool valid = near && (zp >= 1.0f) && (zp <= 100.0f);

        if (__any_sync(0xffffffffu, valid)) {
            const float4 r4 = fr[f * 7 + 4];
            const float4 r5 = fr[f * 7 + 5];
            const float4 r6 = fr[f * 7 + 6];

            const float zn = (100.0f - zp) * (1.0f / 99.0f);
            const float mnew = valid ? fmaxf(m, zn) : m;
            const float sc = fexp2((m - mnew) * K2);
            wsum *= sc; cr *= sc; cg *= sc; cb *= sc;
            m = mnew;

            const float wgt = valid ? (D * fexp2((zn - m) * K2)) : 0.0f;
            wsum += wgt;
            const float w0n = wgt * c0, w1n = wgt * c1, w2n = wgt * c2;
            cr += w0n * r4.x + w1n * r4.w + w2n * r5.z;
            cg += w0n * r4.y + w1n * r5.x + w2n * r5.w;
            cb += w0n * r4.z + w1n * r5.y + w2n * r6.x;
        }
    }

    red[0][wi][lane] = m;
    red[1][wi][lane] = wsum;
    red[2][wi][lane] = cr;
    red[3][wi][lane] = cg;
    red[4][wi][lane] = cb;
    red[5][wi][lane] = pa;
    __syncthreads();

    // ---- Phase 3: parallel combine. thread = (pixel, partial); 8-lane
    //      shfl_xor butterfly per pixel (conflict-free via [8][36] padding). ----
    {
        const int pix  = tid >> 3;
        const int part = tid & 7;
        const float Mv = red[0][part][pix];
        float ws = red[1][part][pix];
        float R  = red[2][part][pix];
        float G  = red[3][part][pix];
        float B  = red[4][part][pix];
        float P  = red[5][part][pix];

        float M = Mv;
        #pragma unroll
        for (int d = 4; d; d >>= 1)
            M = fmaxf(M, __shfl_xor_sync(0xffffffffu, M, d, 8));

        const float sc = fexp2((Mv - M) * K2);
        ws *= sc; R *= sc; G *= sc; B *= sc;

        #pragma unroll
        for (int d = 4; d; d >>= 1) {
            ws += __shfl_xor_sync(0xffffffffu, ws, d, 8);
            R  += __shfl_xor_sync(0xffffffffu, R,  d, 8);
            G  += __shfl_xor_sync(0xffffffffu, G,  d, 8);
            B  += __shfl_xor_sync(0xffffffffu, B,  d, 8);
            P  *= __shfl_xor_sync(0xffffffffu, P,  d, 8);
        }

        if (part == 0) {
            const float wbg  = fexp2((F_EPS - M) * K2);
            const float invd = frcp_nr(ws + wbg);

            const int plx = pix & 7, ply = pix >> 3;
            const int pw = tx * 8 + plx, ph = ty * 4 + ply;
            const int obase = ((batch * 4) * 128 + ph) * 128 + pw;
            out[obase + 0 * 128 * 128] = R * invd;
            out[obase + 1 * 128 * 128] = G * invd;
            out[obase + 2 * 128 * 128] = B * invd;
            out[obase + 3 * 128 * 128] = 1.0f - P;
        }
    }

    // ---- Epilogue: last block resets the flags for the next launch ----
    if (tid == 0) {
        __threadfence();
        const int d = atomicAdd(&g_done, 1);
        if (d == NBLK - 1) {
            g_ready = 0;
            g_done  = 0;
            __threadfence();
        }
    }
}

// ---------------------------------------------------------------------------
extern "C" void kernel_launch(void* const* d_in, const int* in_sizes, int n_in,
                              void* d_out, int out_size) {
    const float* fv  = (const float*)d_in[0];   // [2,1024,3,3]
    const float* tex = (const float*)d_in[1];   // [2,1024,3,3]
    float* out = (float*)d_out;                 // [2,4,128,128]

    fused_kernel<<<NBLK, 256>>>(fv, tex, out);
}

// round 15
// speedup vs baseline: 1.3179x; 1.3179x over previous
#include <cuda_runtime.h>
#include <cstdint>

#define NFACE 1024
#define NB 2

// Preprocessed per-face records (7 x float4) + dilated bboxes.
__device__ float4 g_face[NB * NFACE * 7];
__device__ float4 g_bbox[NB * NFACE];

// Constants: SIGMA=1e-5, GAMMA=1e-4, EPS=1e-3, NEAR=1, FAR=100, DIST_EPS=1e-4
#define F_EPS   1e-3f
#define K2      14426.950408889634f     /* log2(e)/GAMMA */
#define CSIG    144269.50408889634f     /* log2(e)/SIGMA */
#define THR     9.2102404e-05f          /* SIGMA*ln(1/DIST_EPS - 1) */
#define BB_PAD  0.0096f                 /* >= sqrt(THR) */
#define DY4     0.0625f                 /* 4 pixel rows in NDC = 8/128 */

__device__ __forceinline__ float fexp2(float x) {
    float y; asm("ex2.approx.ftz.f32 %0, %1;" : "=f"(y) : "f"(x)); return y;
}
__device__ __forceinline__ float frcp(float x) {
    float y; asm("rcp.approx.ftz.f32 %0, %1;" : "=f"(y) : "f"(x)); return y;
}
__device__ __forceinline__ float frcp_nr(float x) {
    float r = frcp(x);
    return r * (2.0f - x * r);
}

// ---------------------------------------------------------------------------
// Kernel 1: per-face preprocessing (identical to the proven R2 version).
// ---------------------------------------------------------------------------
__global__ void prep_kernel(const float* __restrict__ fv,
                            const float* __restrict__ tex) {
    int i = blockIdx.x * blockDim.x + threadIdx.x;
    if (i >= NB * NFACE) return;
    const float* v = fv + i * 9;
    float x0 = v[0], y0 = v[1], z0 = v[2];
    float x1 = v[3], y1 = v[4], z1 = v[5];
    float x2 = v[6], y2 = v[7], z2 = v[8];

    float e1x = x1 - x0, e1y = y1 - y0;
    float e2x = x2 - x0, e2y = y2 - y0;
    float det = e1x * e2y - e1y * e2x;
    if (fabsf(det) < 1e-10f) det = 1e-10f;
    float inv = 1.0f / det;

    float e12x = x2 - x1, e12y = y2 - y1;
    float e20x = x0 - x2, e20y = y0 - y2;
    float iL01 = 1.0f / fmaxf(e1x * e1x + e1y * e1y, 1e-12f);
    float iL12 = 1.0f / fmaxf(e12x * e12x + e12y * e12y, 1e-12f);
    float iL20 = 1.0f / fmaxf(e20x * e20x + e20y * e20y, 1e-12f);

    const float* t = tex + i * 9;
    float4* fr = g_face + i * 7;
    fr[0] = make_float4(x0, y0, x1, y1);
    fr[1] = make_float4(x2, y2, e2y * inv, e2x * inv);
    fr[2] = make_float4(e1x * inv, e1y * inv, iL01, iL12);
    fr[3] = make_float4(iL20, 1.0f / z0, 1.0f / z1, 1.0f / z2);
    fr[4] = make_float4(t[0], t[1], t[2], t[3]);
    fr[5] = make_float4(t[4], t[5], t[6], t[7]);
    fr[6] = make_float4(t[8], 0.0f, 0.0f, 0.0f);

    float xmn = fminf(x0, fminf(x1, x2)) - BB_PAD;
    float xmx = fmaxf(x0, fmaxf(x1, x2)) + BB_PAD;
    float ymn = fminf(y0, fminf(y1, y2)) - BB_PAD;
    float ymx = fmaxf(y0, fmaxf(y1, y2)) + BB_PAD;
    g_bbox[i] = make_float4(xmn, ymn, xmx, ymx);
}

// ---------------------------------------------------------------------------
// Kernel 2: rasterize, 2 pixels per thread.
// Grid: NB*256 blocks (8x8 px tiles), 256 threads (8 warps).
// Pixel A = (lx, ly), pixel B = (lx, ly+4): same px/dx, shared face loads,
// shared votes. Phase 1: cull (each warp 128 faces). Phase 3: 64 threads
// combine one pixel each (8 partials).
// ---------------------------------------------------------------------------
__global__ void __launch_bounds__(256)
raster_kernel(float* __restrict__ out) {
    __shared__ unsigned short seg[8][128];
    __shared__ unsigned short flat[NFACE];
    __shared__ int counts[8];
    __shared__ float red[6][8][64];   // [field][warp][pixel-in-tile]

    const int tid  = threadIdx.x;
    const int lane = tid & 31;
    const int wi   = tid >> 5;

    const int bidx  = blockIdx.x;
    const int batch = bidx >> 8;          // 256 tiles per batch
    const int tile  = bidx & 255;
    const int tx    = tile & 15;          // 16 tiles across (8 px wide)
    const int ty    = tile >> 4;          // 16 tiles down   (8 px tall)

    const int lx = lane & 7;
    const int ly = lane >> 3;             // 0..3 ; pixel B row = ly+4
    const float px  = (float)(2 * (tx * 8 + lx) + 1 - 128) * (1.0f / 128.0f);
    const float pyA = -(float)(2 * (ty * 8 + ly) + 1 - 128) * (1.0f / 128.0f);
    const float pyB = pyA - DY4;

    const float txmin = (float)(2 * (tx * 8) + 1 - 128) * (1.0f / 128.0f);
    const float txmax = (float)(2 * (tx * 8 + 7) + 1 - 128) * (1.0f / 128.0f);
    const float tymax = -(float)(2 * (ty * 8) + 1 - 128) * (1.0f / 128.0f);
    const float tymin = -(float)(2 * (ty * 8 + 7) + 1 - 128) * (1.0f / 128.0f);

    const float4* __restrict__ bb = g_bbox + batch * NFACE;
    const float4* __restrict__ fr = g_face + (size_t)batch * NFACE * 7;

    // ---- Phase 1: lane-parallel bbox cull + deterministic compaction ----
    const int f0 = wi * 128;
    int cnt = 0;
    #pragma unroll
    for (int it = 0; it < 4; ++it) {
        const int f = f0 + it * 32 + lane;
        const float4 b = __ldg(bb + f);
        const bool hit = !(b.x > txmax || b.z < txmin || b.y > tymax || b.w < tymin);
        const unsigned msk = __ballot_sync(0xffffffffu, hit);
        if (hit) {
            const int pos = cnt + __popc(msk & ((1u << lane) - 1u));
            seg[wi][pos] = (unsigned short)f;
        }
        cnt += __popc(msk);
    }
    if (lane == 0) counts[wi] = cnt;
    __syncthreads();

    int base = 0, T = 0;
    #pragma unroll
    for (int i = 0; i < 8; ++i) {
        const int c = counts[i];
        if (i < wi) base += c;
        T += c;
    }
    for (int k = lane; k < cnt; k += 32) flat[base + k] = seg[wi][k];
    __syncthreads();

    // ---- Phase 2: eval, 2 pixels per thread, warps round-robin ----
    float mA = F_EPS, wsA = 0.0f, crA = 0.0f, cgA = 0.0f, cbA = 0.0f, paA = 1.0f;
    float mB = F_EPS, wsB = 0.0f, crB = 0.0f, cgB = 0.0f, cbB = 0.0f, paB = 1.0f;

    for (int j = wi; j < T; j += 8) {
        const int f = flat[j];

        const float4 r0 = __ldg(fr + f * 7 + 0);
        const float4 r1 = __ldg(fr + f * 7 + 1);
        const float4 r2 = __ldg(fr + f * 7 + 2);
        const float4 r3 = __ldg(fr + f * 7 + 3);

        const float x0 = r0.x, y0 = r0.y, x1 = r0.z, y1 = r0.w;
        const float x2 = r1.x, y2 = r1.y;

        const float e01x = x1 - x0, e01y = y1 - y0;
        const float e12x = x2 - x1, e12y = y2 - y1;
        const float e20x = x0 - x2, e20y = y0 - y2;
        const float dx  = px - x0;
        const float dx1 = px - x1;
        const float dx2 = px - x2;

        // ----- pixel A -----
        const float dyA  = pyA - y0;
        const float w1A = dx * r1.z - dyA * r1.w;
        const float w2A = dyA * r2.x - dx * r2.y;
        const float w0A = 1.0f - w1A - w2A;
        const bool insA = (w0A >= 0.0f) && (w1A >= 0.0f) && (w2A >= 0.0f);

        float t  = __saturatef((dx * e01x + dyA * e01y) * r2.z);
        float qx = dx - t * e01x, qy = dyA - t * e01y;
        float disA = qx * qx + qy * qy;
        const float dy1A = pyA - y1;
        t  = __saturatef((dx1 * e12x + dy1A * e12y) * r2.w);
        qx = dx1 - t * e12x; qy = dy1A - t * e12y;
        disA = fminf(disA, qx * qx + qy * qy);
        const float dy2A = pyA - y2;
        t  = __saturatef((dx2 * e20x + dy2A * e20y) * r3.x);
        qx = dx2 - t * e20x; qy = dy2A - t * e20y;
        disA = fminf(disA, qx * qx + qy * qy);
        const bool nearA = insA || (disA <= THR);

        // ----- pixel B -----
        const float dyB  = pyB - y0;
        const float w1B = dx * r1.z - dyB * r1.w;
        const float w2B = dyB * r2.x - dx * r2.y;
        const float w0B = 1.0f - w1B - w2B;
        const bool insB = (w0B >= 0.0f) && (w1B >= 0.0f) && (w2B >= 0.0f);

        t  = __saturatef((dx * e01x + dyB * e01y) * r2.z);
        qx = dx - t * e01x; qy = dyB - t * e01y;
        float disB = qx * qx + qy * qy;
        const float dy1B = pyB - y1;
        t  = __saturatef((dx1 * e12x + dy1B * e12y) * r2.w);
        qx = dx1 - t * e12x; qy = dy1B - t * e12y;
        disB = fminf(disB, qx * qx + qy * qy);
        const float dy2B = pyB - y2;
        t  = __saturatef((dx2 * e20x + dy2B * e20y) * r3.x);
        qx = dx2 - t * e20x; qy = dy2B - t * e20y;
        disB = fminf(disB, qx * qx + qy * qy);
        const bool nearB = insB || (disB <= THR);

        if (__all_sync(0xffffffffu, !nearA && !nearB)) continue;

        const float DA = frcp(1.0f + fexp2(insA ? (-disA * CSIG) : (disA * CSIG)));
        const float DB = frcp(1.0f + fexp2(insB ? (-disB * CSIG) : (disB * CSIG)));
        paA *= nearA ? (1.0f - DA) : 1.0f;
        paB *= nearB ? (1.0f - DB) : 1.0f;

        float c0A = __saturatef(w0A), c1A = __saturatef(w1A), c2A = __saturatef(w2A);
        const float rsA = frcp_nr(fmaxf(c0A + c1A + c2A, 1e-5f));
        c0A *= rsA; c1A *= rsA; c2A *= rsA;
        float c0B = __saturatef(w0B), c1B = __saturatef(w1B), c2B = __saturatef(w2B);
        const float rsB = frcp_nr(fmaxf(c0B + c1B + c2B, 1e-5f));
        c0B *= rsB; c1B *= rsB; c2B *= rsB;

        const float zpA = frcp_nr(fmaxf(c0A * r3.y + c1A * r3.z + c2A * r3.w, 1e-8f));
        const float zpB = frcp_nr(fmaxf(c0B * r3.y + c1B * r3.z + c2B * r3.w, 1e-8f));
        const bool validA = nearA && (zpA >= 1.0f) && (zpA <= 100.0f);
        const bool validB = nearB && (zpB >= 1.0f) && (zpB <= 100.0f);

        if (__any_sync(0xffffffffu, validA || validB)) {
            const float4 r4 = __ldg(fr + f * 7 + 4);
            const float4 r5 = __ldg(fr + f * 7 + 5);
            const float4 r6 = __ldg(fr + f * 7 + 6);

            // pixel A accumulate
            {
                const float zn = (100.0f - zpA) * (1.0f / 99.0f);
                const float mnew = validA ? fmaxf(mA, zn) : mA;
                const float sc = fexp2((mA - mnew) * K2);
                wsA *= sc; crA *= sc; cgA *= sc; cbA *= sc;
                mA = mnew;
                const float wgt = validA ? (DA * fexp2((zn - mA) * K2)) : 0.0f;
                wsA += wgt;
                const float w0n = wgt * c0A, w1n = wgt * c1A, w2n = wgt * c2A;
                crA += w0n * r4.x + w1n * r4.w + w2n * r5.z;
                cgA += w0n * r4.y + w1n * r5.x + w2n * r5.w;
                cbA += w0n * r4.z + w1n * r5.y + w2n * r6.x;
            }
            // pixel B accumulate
            {
                const float zn = (100.0f - zpB) * (1.0f / 99.0f);
                const float mnew = validB ? fmaxf(mB, zn) : mB;
                const float sc = fexp2((mB - mnew) * K2);
                wsB *= sc; crB *= sc; cgB *= sc; cbB *= sc;
                mB = mnew;
                const float wgt = validB ? (DB * fexp2((zn - mB) * K2)) : 0.0f;
                wsB += wgt;
                const float w0n = wgt * c0B, w1n = wgt * c1B, w2n = wgt * c2B;
                crB += w0n * r4.x + w1n * r4.w + w2n * r5.z;
                cgB += w0n * r4.y + w1n * r5.x + w2n * r5.w;
                cbB += w0n * r4.z + w1n * r5.y + w2n * r6.x;
            }
        }
    }

    // stash partials: pixel id within 8x8 tile = row*8+lx (A: row=ly, B: row=ly+4)
    const int pidA = ly * 8 + lx;
    const int pidB = (ly + 4) * 8 + lx;
    red[0][wi][pidA] = mA;  red[0][wi][pidB] = mB;
    red[1][wi][pidA] = wsA; red[1][wi][pidB] = wsB;
    red[2][wi][pidA] = crA; red[2][wi][pidB] = crB;
    red[3][wi][pidA] = cgA; red[3][wi][pidB] = cgB;
    red[4][wi][pidA] = cbA; red[4][wi][pidB] = cbB;
    red[5][wi][pidA] = paA; red[5][wi][pidB] = paB;
    __syncthreads();

    // ---- Phase 3: threads 0..63 combine one pixel each (8 partials) ----
    if (tid < 64) {
        float M = F_EPS;
        #pragma unroll
        for (int i = 0; i < 8; ++i) M = fmaxf(M, red[0][i][tid]);
        float ws = 0.0f, R = 0.0f, G = 0.0f, B = 0.0f, P = 1.0f;
        #pragma unroll
        for (int i = 0; i < 8; ++i) {
            const float sc = fexp2((red[0][i][tid] - M) * K2);
            ws += red[1][i][tid] * sc;
            R  += red[2][i][tid] * sc;
            G  += red[3][i][tid] * sc;
            B  += red[4][i][tid] * sc;
            P  *= red[5][i][tid];
        }
        const float wbg  = fexp2((F_EPS - M) * K2);
        const float invd = frcp_nr(ws + wbg);

        const int plx = tid & 7, ply = tid >> 3;
        const int pw = tx * 8 + plx, ph = ty * 8 + ply;
        const int obase = ((batch * 4) * 128 + ph) * 128 + pw;
        out[obase + 0 * 128 * 128] = R * invd;
        out[obase + 1 * 128 * 128] = G * invd;
        out[obase + 2 * 128 * 128] = B * invd;
        out[obase + 3 * 128 * 128] = 1.0f - P;
    }
}

// ---------------------------------------------------------------------------
extern "C" void kernel_launch(void* const* d_in, const int* in_sizes, int n_in,
                              void* d_out, int out_size) {
    const float* fv  = (const float*)d_in[0];   // [2,1024,3,3]
    const float* tex = (const float*)d_in[1];   // [2,1024,3,3]
    float* out = (float*)d_out;                 // [2,4,128,128]

    prep_kernel<<<(NB * NFACE + 127) / 128, 128>>>(fv, tex);
    raster_kernel<<<NB * 256, 256>>>(out);
}